// round 2
// baseline (speedup 1.0000x reference)
#include <cuda_runtime.h>
#include <cuda_bf16.h>

// Problem dims (fixed by the dataset)
#define BB 2
#define DD 10
#define HH 512
#define WW 512
#define CH 4            // h-values processed per thread (rolling window)

// Output layout: coords (B, 3, D, H, W) followed by y (B, D, H, W)

struct Row { float lf; float4 m; float rt; };

// Load one row segment: aligned float4 + neighbor edges via warp shuffle.
// Only warp-boundary lanes issue (single-lane) scalar loads.
__device__ __forceinline__ Row load_row(const float* __restrict__ rowptr, int w0, int lane) {
    Row r;
    r.m  = *reinterpret_cast<const float4*>(rowptr + w0);
    r.lf = __shfl_up_sync(0xffffffffu, r.m.w, 1);
    r.rt = __shfl_down_sync(0xffffffffu, r.m.x, 1);
    if (lane == 0)  r.lf = (w0 == 0)        ? r.m.x : __ldg(rowptr + w0 - 1);
    if (lane == 31) r.rt = (w0 + 4 >= WW)   ? r.m.w : __ldg(rowptr + w0 + 4);
    return r;
}

__device__ __forceinline__ float rget(const Row& r, int k) {
    switch (k) {
        case 0:  return r.lf;
        case 1:  return r.m.x;
        case 2:  return r.m.y;
        case 3:  return r.m.z;
        case 4:  return r.m.w;
        default: return r.rt;
    }
}

__global__ __launch_bounds__(256)
void quadinterp3d_kernel(const float* __restrict__ x, float* __restrict__ out) {
    const int gid  = blockIdx.x * blockDim.x + threadIdx.x;
    const int lane = threadIdx.x & 31;
    // threads = B*D*(H/CH)*(W/4) = 2*10*128*128 = 327,680
    const int w4 = gid & 127;           // W/4 = 128 (consecutive within a warp)
    const int hb = (gid >> 7) & 127;    // H/CH = 128
    const int t  = gid >> 14;           // 0..19 (B*D)
    const int d  = t % DD;
    const int b  = t / DD;
    const int w0 = w4 << 2;
    const int h0 = hb * CH;

    // Clamped d-plane base pointers
    const float* pl[3];
    #pragma unroll
    for (int p = 0; p < 3; p++) {
        int zz = min(max(d + p - 1, 0), DD - 1);
        pl[p] = x + ((size_t)(b * DD + zz) * HH) * WW;
    }

    // rows[p*3 + dy]: dy 0 = h-1, 1 = h, 2 = h+1 (matches v[] indexing of R1)
    Row rows[9];
    {
        const int hm1 = max(h0 - 1, 0);
        #pragma unroll
        for (int p = 0; p < 3; p++) {
            rows[p * 3 + 0] = load_row(pl[p] + (size_t)hm1 * WW, w0, lane);
            rows[p * 3 + 1] = load_row(pl[p] + (size_t)h0  * WW, w0, lane);
        }
    }

    const size_t plsz = (size_t)DD * HH * WW;
    const size_t obase0 = (size_t)(b * 3 + 0) * plsz;
    const size_t obase1 = (size_t)(b * 3 + 1) * plsz;
    const size_t obase2 = (size_t)(b * 3 + 2) * plsz;
    const size_t obasey = (size_t)BB * 3 * plsz + (size_t)b * plsz;

    #pragma unroll
    for (int hh = 0; hh < CH; hh++) {
        const int h  = h0 + hh;
        const int hp = min(h + 1, HH - 1);

        // Fetch the 3 new h+1 rows
        #pragma unroll
        for (int p = 0; p < 3; p++)
            rows[p * 3 + 2] = load_row(pl[p] + (size_t)hp * WW, w0, lane);

        float yv[4], ck0[4], ck1[4], ck2[4];

        #pragma unroll
        for (int j = 0; j < 4; j++) {
            const float cc = rget(rows[4], j + 1);

            float nmax = 0.0f;
            #pragma unroll
            for (int r = 0; r < 9; r++) {
                #pragma unroll
                for (int k = 0; k < 3; k++) {
                    if (r == 4 && k == 1) continue;
                    nmax = fmaxf(nmax, rget(rows[r], j + k));
                }
            }
            const bool m = cc > nmax;

            float dx0 = 0.0f, dx1 = 0.0f, dx2 = 0.0f;
            float yval = cc;

            if (m) {
                const float gx = 0.5f * (rget(rows[4], j + 2) - rget(rows[4], j));
                const float gy = 0.5f * (rget(rows[5], j + 1) - rget(rows[3], j + 1));
                const float gs = 0.5f * (rget(rows[7], j + 1) - rget(rows[1], j + 1));

                const float dxx = rget(rows[4], j) + rget(rows[4], j + 2) - 2.0f * cc;
                const float dyy = rget(rows[3], j + 1) + rget(rows[5], j + 1) - 2.0f * cc;
                const float dss = rget(rows[1], j + 1) + rget(rows[7], j + 1) - 2.0f * cc;
                const float dxy = 0.25f * (rget(rows[3], j) + rget(rows[5], j + 2)
                                         - rget(rows[5], j) - rget(rows[3], j + 2));
                const float dys = 0.25f * (rget(rows[0], j + 1) + rget(rows[8], j + 1)
                                         - rget(rows[6], j + 1) - rget(rows[2], j + 1));
                const float dxs = 0.25f * (rget(rows[1], j) + rget(rows[7], j + 2)
                                         - rget(rows[7], j) - rget(rows[1], j + 2));

                const float h00 = dxx, h01 = dxy, h02 = dxs;
                const float h10 = dxy, h11 = dyy, h12 = dys;
                const float h20 = dxs, h21 = dys, h22 = dss;
                const float b0 = gx, b1 = gy, b2 = gs;

                const float c00 = h11 * h22 - h12 * h21;
                const float c01 = h10 * h22 - h12 * h20;
                const float c02 = h10 * h21 - h11 * h20;
                const float det = h00 * c00 - h01 * c01 + h02 * c02;

                const float t1 = b1 * h22 - h12 * b2;
                const float t2 = b1 * h21 - h11 * b2;
                const float t3 = h10 * b2 - b1 * h20;

                const float inv = 1.0f / det;
                const float sx = (b0 * c00 - h01 * t1 + h02 * t2) * inv;
                const float sy = (h00 * t1 - b0 * c01 + h02 * t3) * inv;
                const float ss = (h00 * (h11 * b2 - h21 * b1) - h01 * t3 + b0 * c02) * inv;

                dx0 = -sx; dx1 = -sy; dx2 = -ss;

                const float far = fmaxf(fmaxf(fabsf(dx0), fabsf(dx1)), fabsf(dx2));
                if (far > 0.7f) { dx0 = 0.0f; dx1 = 0.0f; dx2 = 0.0f; }

                yval = cc + 0.5f * (gx * dx0 + gy * dx1 + gs * dx2) + 10.0f;
            }

            yv[j]  = yval;
            ck0[j] = (float)d + dx2;
            ck1[j] = (float)h + dx1;
            ck2[j] = (float)(w0 + j) + dx0;
        }

        const size_t inner = ((size_t)d * HH + h) * WW + w0;
        *reinterpret_cast<float4*>(out + obase0 + inner) = make_float4(ck0[0], ck0[1], ck0[2], ck0[3]);
        *reinterpret_cast<float4*>(out + obase1 + inner) = make_float4(ck1[0], ck1[1], ck1[2], ck1[3]);
        *reinterpret_cast<float4*>(out + obase2 + inner) = make_float4(ck2[0], ck2[1], ck2[2], ck2[3]);
        *reinterpret_cast<float4*>(out + obasey + inner) = make_float4(yv[0], yv[1], yv[2], yv[3]);

        // Roll the window: h-1 <- h, h <- h+1
        #pragma unroll
        for (int p = 0; p < 3; p++) {
            rows[p * 3 + 0] = rows[p * 3 + 1];
            rows[p * 3 + 1] = rows[p * 3 + 2];
        }
    }
}

extern "C" void kernel_launch(void* const* d_in, const int* in_sizes, int n_in,
                              void* d_out, int out_size) {
    const float* x = (const float*)d_in[0];
    float* out = (float*)d_out;
    const int total_threads = BB * DD * (HH / CH) * (WW / 4);  // 327,680
    const int block = 256;
    const int grid = total_threads / block;                    // 1,280
    quadinterp3d_kernel<<<grid, block>>>(x, out);
}

// round 3
// speedup vs baseline: 1.1490x; 1.1490x over previous
#include <cuda_runtime.h>
#include <cuda_bf16.h>

#define BB 2
#define DD 10
#define HH 512
#define WW 512

__device__ __forceinline__ float4 fmax4(float4 a, float4 b) {
    return make_float4(fmaxf(a.x, b.x), fmaxf(a.y, b.y), fmaxf(a.z, b.z), fmaxf(a.w, b.w));
}

// 3x3 Newton solve at a detected maximum. Same algebra as the verified R1 kernel.
__device__ __forceinline__ void newton_step(
    float cc,
    float a4, float c4,                    // row4 (d,h)     at j, j+2
    float a3, float b3, float c3,          // row3 (d,h-1)   at j, j+1, j+2
    float a5, float b5, float c5,          // row5 (d,h+1)
    float a1, float b1v, float c1,         // row1 (d-1,h)
    float a7, float b7, float c7,          // row7 (d+1,h)
    float e0, float e2, float e6, float e8,// rows 0,2,6,8 at j+1
    float& dx0, float& dx1, float& dx2, float& yv)
{
    const float gx = 0.5f * (c4 - a4);
    const float gy = 0.5f * (b5 - b3);
    const float gs = 0.5f * (b7 - b1v);

    const float dxx = a4 + c4 - 2.0f * cc;
    const float dyy = b3 + b5 - 2.0f * cc;
    const float dss = b1v + b7 - 2.0f * cc;
    const float dxy = 0.25f * (a3 + c5 - a5 - c3);
    const float dys = 0.25f * (e0 + e8 - e6 - e2);
    const float dxs = 0.25f * (a1 + c7 - a7 - c1);

    const float h00 = dxx, h01 = dxy, h02 = dxs;
    const float h10 = dxy, h11 = dyy, h12 = dys;
    const float h20 = dxs, h21 = dys, h22 = dss;
    const float b0 = gx, b1 = gy, b2 = gs;

    const float c00 = h11 * h22 - h12 * h21;
    const float c01 = h10 * h22 - h12 * h20;
    const float c02 = h10 * h21 - h11 * h20;
    const float det = h00 * c00 - h01 * c01 + h02 * c02;

    const float t1 = b1 * h22 - h12 * b2;
    const float t2 = b1 * h21 - h11 * b2;
    const float t3 = h10 * b2 - b1 * h20;

    const float inv = 1.0f / det;
    const float sx = (b0 * c00 - h01 * t1 + h02 * t2) * inv;
    const float sy = (h00 * t1 - b0 * c01 + h02 * t3) * inv;
    const float ss = (h00 * (h11 * b2 - h21 * b1) - h01 * t3 + b0 * c02) * inv;

    float d0 = -sx, d1 = -sy, d2 = -ss;
    const float far = fmaxf(fmaxf(fabsf(d0), fabsf(d1)), fabsf(d2));
    if (far > 0.7f) { d0 = 0.0f; d1 = 0.0f; d2 = 0.0f; }

    dx0 = d0; dx1 = d1; dx2 = d2;
    yv = cc + 0.5f * (gx * d0 + gy * d1 + gs * d2) + 10.0f;
}

__global__ __launch_bounds__(256)
void quadinterp3d_kernel(const float* __restrict__ x, float* __restrict__ out) {
    const int gid  = blockIdx.x * blockDim.x + threadIdx.x;
    const int lane = threadIdx.x & 31;
    const int w4 = gid & 127;            // W/4 = 128 (consecutive within a warp)
    const int h  = (gid >> 7) & 511;
    const int t  = gid >> 16;            // 0..19 (B*D)
    const int d  = t % DD;
    const int b  = t / DD;
    const int w0 = w4 << 2;

    const int hm = max(h - 1, 0), hp = min(h + 1, HH - 1);
    const int zm = max(d - 1, 0), zp = min(d + 1, DD - 1);

    const float* __restrict__ base = x + (size_t)b * DD * HH * WW;
    int off[9];
    off[0] = (zm * HH + hm) * WW;  off[1] = (zm * HH + h) * WW;  off[2] = (zm * HH + hp) * WW;
    off[3] = (d  * HH + hm) * WW;  off[4] = (d  * HH + h) * WW;  off[5] = (d  * HH + hp) * WW;
    off[6] = (zp * HH + hm) * WW;  off[7] = (zp * HH + h) * WW;  off[8] = (zp * HH + hp) * WW;

    // Batched, independent loads: one aligned float4 per stencil row (MLP=9)
    float4 v[9];
    #pragma unroll
    for (int r = 0; r < 9; r++)
        v[r] = *reinterpret_cast<const float4*>(base + off[r] + w0);

    // Column max of the 8 non-center rows (for the strict-local-max mask)
    float4 cm = v[0];
    cm = fmax4(cm, v[1]); cm = fmax4(cm, v[2]); cm = fmax4(cm, v[3]);
    cm = fmax4(cm, v[5]); cm = fmax4(cm, v[6]); cm = fmax4(cm, v[7]); cm = fmax4(cm, v[8]);

    // Edge columns via warp shuffle (loads already issued; shuffles are batched, not per-iteration)
    float cmL = __shfl_up_sync(0xffffffffu,  cm.w, 1);
    float cmR = __shfl_down_sync(0xffffffffu, cm.x, 1);
    float r4l = __shfl_up_sync(0xffffffffu,  v[4].w, 1);
    float r4r = __shfl_down_sync(0xffffffffu, v[4].x, 1);

    // Warp-boundary fixups (lanes 0 / 31 only; replicate-pad = clamped index)
    if (lane == 0) {
        if (w0 == 0) { cmL = cm.x; r4l = v[4].x; }
        else {
            const int wl = w0 - 1;
            r4l = __ldg(base + off[4] + wl);
            float q =       fmaxf(__ldg(base + off[0] + wl), __ldg(base + off[1] + wl));
            q = fmaxf(q,    fmaxf(__ldg(base + off[2] + wl), __ldg(base + off[3] + wl)));
            q = fmaxf(q,    fmaxf(__ldg(base + off[5] + wl), __ldg(base + off[6] + wl)));
            q = fmaxf(q,    fmaxf(__ldg(base + off[7] + wl), __ldg(base + off[8] + wl)));
            cmL = q;
        }
    }
    if (lane == 31) {
        if (w0 + 4 >= WW) { cmR = cm.w; r4r = v[4].w; }
        else {
            const int wr = w0 + 4;
            r4r = __ldg(base + off[4] + wr);
            float q =       fmaxf(__ldg(base + off[0] + wr), __ldg(base + off[1] + wr));
            q = fmaxf(q,    fmaxf(__ldg(base + off[2] + wr), __ldg(base + off[3] + wr)));
            q = fmaxf(q,    fmaxf(__ldg(base + off[5] + wr), __ldg(base + off[6] + wr)));
            q = fmaxf(q,    fmaxf(__ldg(base + off[7] + wr), __ldg(base + off[8] + wr)));
            cmR = q;
        }
    }

    // Windowed max over the 6-wide cm vector [cmL, cm.x, cm.y, cm.z, cm.w, cmR]
    const float p01 = fmaxf(cmL,  cm.x);
    const float p12 = fmaxf(cm.x, cm.y);
    const float p23 = fmaxf(cm.y, cm.z);
    const float p34 = fmaxf(cm.z, cm.w);
    const float win0 = fmaxf(p01, cm.y);
    const float win1 = fmaxf(p12, cm.z);
    const float win2 = fmaxf(p23, cm.w);
    const float win3 = fmaxf(p34, cmR);

    // Center-row contribution (excludes the center element itself)
    const float u0 = r4l, u1 = v[4].x, u2 = v[4].y, u3 = v[4].z, u4 = v[4].w, u5 = r4r;
    const float nm0 = fmaxf(fmaxf(win0, fmaxf(u0, u2)), 0.0f);
    const float nm1 = fmaxf(fmaxf(win1, fmaxf(u1, u3)), 0.0f);
    const float nm2 = fmaxf(fmaxf(win2, fmaxf(u2, u4)), 0.0f);
    const float nm3 = fmaxf(fmaxf(win3, fmaxf(u3, u5)), 0.0f);

    const bool m0 = u1 > nm0;
    const bool m1 = u2 > nm1;
    const bool m2 = u3 > nm2;
    const bool m3 = u4 > nm3;

    float A0 = 0.f, B0 = 0.f, C0 = 0.f, y0 = u1;
    float A1 = 0.f, B1 = 0.f, C1 = 0.f, y1 = u2;
    float A2 = 0.f, B2 = 0.f, C2 = 0.f, y2 = u3;
    float A3 = 0.f, B3 = 0.f, C3 = 0.f, y3 = u4;

    // Heavy path: rare (strict local maxima). Edge values for j=0/3 loaded lazily (L1 hits).
    if (m0) {
        const int wl = (w0 == 0) ? 0 : (w0 - 1);
        const float a1 = __ldg(base + off[1] + wl);
        const float a3 = __ldg(base + off[3] + wl);
        const float a5 = __ldg(base + off[5] + wl);
        const float a7 = __ldg(base + off[7] + wl);
        newton_step(u1, u0, v[4].y,
                    a3, v[3].x, v[3].y,
                    a5, v[5].x, v[5].y,
                    a1, v[1].x, v[1].y,
                    a7, v[7].x, v[7].y,
                    v[0].x, v[2].x, v[6].x, v[8].x,
                    A0, B0, C0, y0);
    }
    if (m1) {
        newton_step(u2, v[4].x, v[4].z,
                    v[3].x, v[3].y, v[3].z,
                    v[5].x, v[5].y, v[5].z,
                    v[1].x, v[1].y, v[1].z,
                    v[7].x, v[7].y, v[7].z,
                    v[0].y, v[2].y, v[6].y, v[8].y,
                    A1, B1, C1, y1);
    }
    if (m2) {
        newton_step(u3, v[4].y, v[4].w,
                    v[3].y, v[3].z, v[3].w,
                    v[5].y, v[5].z, v[5].w,
                    v[1].y, v[1].z, v[1].w,
                    v[7].y, v[7].z, v[7].w,
                    v[0].z, v[2].z, v[6].z, v[8].z,
                    A2, B2, C2, y2);
    }
    if (m3) {
        const int wr = (w0 + 4 >= WW) ? (WW - 1) : (w0 + 4);
        const float c1 = __ldg(base + off[1] + wr);
        const float c3 = __ldg(base + off[3] + wr);
        const float c5 = __ldg(base + off[5] + wr);
        const float c7 = __ldg(base + off[7] + wr);
        newton_step(u4, v[4].z, u5,
                    v[3].z, v[3].w, c3,
                    v[5].z, v[5].w, c5,
                    v[1].z, v[1].w, c1,
                    v[7].z, v[7].w, c7,
                    v[0].w, v[2].w, v[6].w, v[8].w,
                    A3, B3, C3, y3);
    }

    // Coalesced float4 stores: coords (B,3,D,H,W) then y (B,D,H,W)
    const size_t plsz = (size_t)DD * HH * WW;
    const size_t inner = ((size_t)d * HH + h) * WW + w0;
    const float fd = (float)d, fh = (float)h, fw = (float)w0;
    *reinterpret_cast<float4*>(out + (size_t)(b * 3 + 0) * plsz + inner) =
        make_float4(fd + C0, fd + C1, fd + C2, fd + C3);
    *reinterpret_cast<float4*>(out + (size_t)(b * 3 + 1) * plsz + inner) =
        make_float4(fh + B0, fh + B1, fh + B2, fh + B3);
    *reinterpret_cast<float4*>(out + (size_t)(b * 3 + 2) * plsz + inner) =
        make_float4(fw + A0, fw + 1.0f + A1, fw + 2.0f + A2, fw + 3.0f + A3);
    *reinterpret_cast<float4*>(out + (size_t)BB * 3 * plsz + (size_t)b * plsz + inner) =
        make_float4(y0, y1, y2, y3);
}

extern "C" void kernel_launch(void* const* d_in, const int* in_sizes, int n_in,
                              void* d_out, int out_size) {
    const float* x = (const float*)d_in[0];
    float* out = (float*)d_out;
    const int total_threads = BB * DD * HH * (WW / 4);   // 1,310,720
    const int block = 256;
    const int grid = total_threads / block;              // 5,120
    quadinterp3d_kernel<<<grid, block>>>(x, out);
}

// round 4
// speedup vs baseline: 1.3490x; 1.1741x over previous
#include <cuda_runtime.h>
#include <cuda_bf16.h>

#define BB 2
#define DD 10
#define HH 512
#define WW 512

__device__ __forceinline__ float4 fmax4(float4 a, float4 b) {
    return make_float4(fmaxf(a.x, b.x), fmaxf(a.y, b.y), fmaxf(a.z, b.z), fmaxf(a.w, b.w));
}

// 3x3 Newton solve at a detected maximum. Same algebra as the verified R1 kernel.
__device__ __forceinline__ void newton_step(
    float cc,
    float a4, float c4,                    // row4 (d,h)     at j, j+2
    float a3, float b3, float c3,          // row3 (d,h-1)   at j, j+1, j+2
    float a5, float b5, float c5,          // row5 (d,h+1)
    float a1, float b1v, float c1,         // row1 (d-1,h)
    float a7, float b7, float c7,          // row7 (d+1,h)
    float e0, float e2, float e6, float e8,// rows 0,2,6,8 at j+1
    float& dx0, float& dx1, float& dx2, float& yv)
{
    const float gx = 0.5f * (c4 - a4);
    const float gy = 0.5f * (b5 - b3);
    const float gs = 0.5f * (b7 - b1v);

    const float dxx = a4 + c4 - 2.0f * cc;
    const float dyy = b3 + b5 - 2.0f * cc;
    const float dss = b1v + b7 - 2.0f * cc;
    const float dxy = 0.25f * (a3 + c5 - a5 - c3);
    const float dys = 0.25f * (e0 + e8 - e6 - e2);
    const float dxs = 0.25f * (a1 + c7 - a7 - c1);

    const float h00 = dxx, h01 = dxy, h02 = dxs;
    const float h10 = dxy, h11 = dyy, h12 = dys;
    const float h20 = dxs, h21 = dys, h22 = dss;
    const float b0 = gx, b1 = gy, b2 = gs;

    const float c00 = h11 * h22 - h12 * h21;
    const float c01 = h10 * h22 - h12 * h20;
    const float c02 = h10 * h21 - h11 * h20;
    const float det = h00 * c00 - h01 * c01 + h02 * c02;

    const float t1 = b1 * h22 - h12 * b2;
    const float t2 = b1 * h21 - h11 * b2;
    const float t3 = h10 * b2 - b1 * h20;

    const float inv = 1.0f / det;
    const float sx = (b0 * c00 - h01 * t1 + h02 * t2) * inv;
    const float sy = (h00 * t1 - b0 * c01 + h02 * t3) * inv;
    const float ss = (h00 * (h11 * b2 - h21 * b1) - h01 * t3 + b0 * c02) * inv;

    float d0 = -sx, d1 = -sy, d2 = -ss;
    const float far = fmaxf(fmaxf(fabsf(d0), fabsf(d1)), fabsf(d2));
    if (far > 0.7f) { d0 = 0.0f; d1 = 0.0f; d2 = 0.0f; }

    dx0 = d0; dx1 = d1; dx2 = d2;
    yv = cc + 0.5f * (gx * d0 + gy * d1 + gs * d2) + 10.0f;
}

__global__ __launch_bounds__(256, 3)   // force <=85 regs: 3 CTAs/SM (occupancy cliff fix)
void quadinterp3d_kernel(const float* __restrict__ x, float* __restrict__ out) {
    const int gid  = blockIdx.x * blockDim.x + threadIdx.x;
    const int lane = threadIdx.x & 31;
    const int w4 = gid & 127;            // W/4 = 128 (consecutive within a warp)
    const int h  = (gid >> 7) & 511;
    const int t  = gid >> 16;            // 0..19 (B*D)
    const int d  = t % DD;
    const int b  = t / DD;
    const int w0 = w4 << 2;

    const int hm = max(h - 1, 0), hp = min(h + 1, HH - 1);
    const int zm = max(d - 1, 0), zp = min(d + 1, DD - 1);

    const float* __restrict__ base = x + (size_t)b * DD * HH * WW;
    int off[9];
    off[0] = (zm * HH + hm) * WW;  off[1] = (zm * HH + h) * WW;  off[2] = (zm * HH + hp) * WW;
    off[3] = (d  * HH + hm) * WW;  off[4] = (d  * HH + h) * WW;  off[5] = (d  * HH + hp) * WW;
    off[6] = (zp * HH + hm) * WW;  off[7] = (zp * HH + h) * WW;  off[8] = (zp * HH + hp) * WW;

    // Batched, independent loads: one aligned float4 per stencil row (MLP=9)
    float4 v[9];
    #pragma unroll
    for (int r = 0; r < 9; r++)
        v[r] = *reinterpret_cast<const float4*>(base + off[r] + w0);

    // Column max of the 8 non-center rows (for the strict-local-max mask)
    float4 cm = v[0];
    cm = fmax4(cm, v[1]); cm = fmax4(cm, v[2]); cm = fmax4(cm, v[3]);
    cm = fmax4(cm, v[5]); cm = fmax4(cm, v[6]); cm = fmax4(cm, v[7]); cm = fmax4(cm, v[8]);

    // Edge columns via warp shuffle (loads already issued; shuffles batched, not per-iteration)
    float cmL = __shfl_up_sync(0xffffffffu,  cm.w, 1);
    float cmR = __shfl_down_sync(0xffffffffu, cm.x, 1);
    float r4l = __shfl_up_sync(0xffffffffu,  v[4].w, 1);
    float r4r = __shfl_down_sync(0xffffffffu, v[4].x, 1);

    // Warp-boundary fixups (lanes 0 / 31 only; replicate-pad = clamped index)
    if (lane == 0) {
        if (w0 == 0) { cmL = cm.x; r4l = v[4].x; }
        else {
            const int wl = w0 - 1;
            r4l = __ldg(base + off[4] + wl);
            float q =       fmaxf(__ldg(base + off[0] + wl), __ldg(base + off[1] + wl));
            q = fmaxf(q,    fmaxf(__ldg(base + off[2] + wl), __ldg(base + off[3] + wl)));
            q = fmaxf(q,    fmaxf(__ldg(base + off[5] + wl), __ldg(base + off[6] + wl)));
            q = fmaxf(q,    fmaxf(__ldg(base + off[7] + wl), __ldg(base + off[8] + wl)));
            cmL = q;
        }
    }
    if (lane == 31) {
        if (w0 + 4 >= WW) { cmR = cm.w; r4r = v[4].w; }
        else {
            const int wr = w0 + 4;
            r4r = __ldg(base + off[4] + wr);
            float q =       fmaxf(__ldg(base + off[0] + wr), __ldg(base + off[1] + wr));
            q = fmaxf(q,    fmaxf(__ldg(base + off[2] + wr), __ldg(base + off[3] + wr)));
            q = fmaxf(q,    fmaxf(__ldg(base + off[5] + wr), __ldg(base + off[6] + wr)));
            q = fmaxf(q,    fmaxf(__ldg(base + off[7] + wr), __ldg(base + off[8] + wr)));
            cmR = q;
        }
    }

    // Windowed max over the 6-wide cm vector [cmL, cm.x, cm.y, cm.z, cm.w, cmR]
    const float p01 = fmaxf(cmL,  cm.x);
    const float p12 = fmaxf(cm.x, cm.y);
    const float p23 = fmaxf(cm.y, cm.z);
    const float p34 = fmaxf(cm.z, cm.w);
    const float win0 = fmaxf(p01, cm.y);
    const float win1 = fmaxf(p12, cm.z);
    const float win2 = fmaxf(p23, cm.w);
    const float win3 = fmaxf(p34, cmR);

    // Center-row contribution (excludes the center element itself)
    const float u0 = r4l, u1 = v[4].x, u2 = v[4].y, u3 = v[4].z, u4 = v[4].w, u5 = r4r;
    const float nm0 = fmaxf(fmaxf(win0, fmaxf(u0, u2)), 0.0f);
    const float nm1 = fmaxf(fmaxf(win1, fmaxf(u1, u3)), 0.0f);
    const float nm2 = fmaxf(fmaxf(win2, fmaxf(u2, u4)), 0.0f);
    const float nm3 = fmaxf(fmaxf(win3, fmaxf(u3, u5)), 0.0f);

    const bool m0 = u1 > nm0;
    const bool m1 = u2 > nm1;
    const bool m2 = u3 > nm2;
    const bool m3 = u4 > nm3;

    float A0 = 0.f, B0 = 0.f, C0 = 0.f, y0 = u1;
    float A1 = 0.f, B1 = 0.f, C1 = 0.f, y1 = u2;
    float A2 = 0.f, B2 = 0.f, C2 = 0.f, y2 = u3;
    float A3 = 0.f, B3 = 0.f, C3 = 0.f, y3 = u4;

    // Heavy path: rare (strict local maxima). Edge values for j=0/3 loaded lazily (L1 hits).
    if (m0) {
        const int wl = (w0 == 0) ? 0 : (w0 - 1);
        const float a1 = __ldg(base + off[1] + wl);
        const float a3 = __ldg(base + off[3] + wl);
        const float a5 = __ldg(base + off[5] + wl);
        const float a7 = __ldg(base + off[7] + wl);
        newton_step(u1, u0, v[4].y,
                    a3, v[3].x, v[3].y,
                    a5, v[5].x, v[5].y,
                    a1, v[1].x, v[1].y,
                    a7, v[7].x, v[7].y,
                    v[0].x, v[2].x, v[6].x, v[8].x,
                    A0, B0, C0, y0);
    }
    if (m1) {
        newton_step(u2, v[4].x, v[4].z,
                    v[3].x, v[3].y, v[3].z,
                    v[5].x, v[5].y, v[5].z,
                    v[1].x, v[1].y, v[1].z,
                    v[7].x, v[7].y, v[7].z,
                    v[0].y, v[2].y, v[6].y, v[8].y,
                    A1, B1, C1, y1);
    }
    if (m2) {
        newton_step(u3, v[4].y, v[4].w,
                    v[3].y, v[3].z, v[3].w,
                    v[5].y, v[5].z, v[5].w,
                    v[1].y, v[1].z, v[1].w,
                    v[7].y, v[7].z, v[7].w,
                    v[0].z, v[2].z, v[6].z, v[8].z,
                    A2, B2, C2, y2);
    }
    if (m3) {
        const int wr = (w0 + 4 >= WW) ? (WW - 1) : (w0 + 4);
        const float c1 = __ldg(base + off[1] + wr);
        const float c3 = __ldg(base + off[3] + wr);
        const float c5 = __ldg(base + off[5] + wr);
        const float c7 = __ldg(base + off[7] + wr);
        newton_step(u4, v[4].z, u5,
                    v[3].z, v[3].w, c3,
                    v[5].z, v[5].w, c5,
                    v[1].z, v[1].w, c1,
                    v[7].z, v[7].w, c7,
                    v[0].w, v[2].w, v[6].w, v[8].w,
                    A3, B3, C3, y3);
    }

    // Coalesced float4 stores: coords (B,3,D,H,W) then y (B,D,H,W)
    const size_t plsz = (size_t)DD * HH * WW;
    const size_t inner = ((size_t)d * HH + h) * WW + w0;
    const float fd = (float)d, fh = (float)h, fw = (float)w0;
    *reinterpret_cast<float4*>(out + (size_t)(b * 3 + 0) * plsz + inner) =
        make_float4(fd + C0, fd + C1, fd + C2, fd + C3);
    *reinterpret_cast<float4*>(out + (size_t)(b * 3 + 1) * plsz + inner) =
        make_float4(fh + B0, fh + B1, fh + B2, fh + B3);
    *reinterpret_cast<float4*>(out + (size_t)(b * 3 + 2) * plsz + inner) =
        make_float4(fw + A0, fw + 1.0f + A1, fw + 2.0f + A2, fw + 3.0f + A3);
    *reinterpret_cast<float4*>(out + (size_t)BB * 3 * plsz + (size_t)b * plsz + inner) =
        make_float4(y0, y1, y2, y3);
}

extern "C" void kernel_launch(void* const* d_in, const int* in_sizes, int n_in,
                              void* d_out, int out_size) {
    const float* x = (const float*)d_in[0];
    float* out = (float*)d_out;
    const int total_threads = BB * DD * HH * (WW / 4);   // 1,310,720
    const int block = 256;
    const int grid = total_threads / block;              // 5,120
    quadinterp3d_kernel<<<grid, block>>>(x, out);
}

// round 5
// speedup vs baseline: 1.5215x; 1.1278x over previous
#include <cuda_runtime.h>
#include <cuda_bf16.h>

#define BB 2
#define DD 10
#define HH 512
#define WW 512

__device__ __forceinline__ float4 fmax4(float4 a, float4 b) {
    return make_float4(fmaxf(a.x, b.x), fmaxf(a.y, b.y), fmaxf(a.z, b.z), fmaxf(a.w, b.w));
}

// 3x3 Newton solve at a detected maximum. Same algebra as the verified kernels.
__device__ __forceinline__ void newton_step(
    float cc,
    float a4, float c4,                    // row4 (d,h)     at j, j+2
    float a3, float b3, float c3,          // row3 (d,h-1)   at j, j+1, j+2
    float a5, float b5, float c5,          // row5 (d,h+1)
    float a1, float b1v, float c1,         // row1 (d-1,h)
    float a7, float b7, float c7,          // row7 (d+1,h)
    float e0, float e2, float e6, float e8,// rows 0,2,6,8 at j+1
    float& dx0, float& dx1, float& dx2, float& yv)
{
    const float gx = 0.5f * (c4 - a4);
    const float gy = 0.5f * (b5 - b3);
    const float gs = 0.5f * (b7 - b1v);

    const float dxx = a4 + c4 - 2.0f * cc;
    const float dyy = b3 + b5 - 2.0f * cc;
    const float dss = b1v + b7 - 2.0f * cc;
    const float dxy = 0.25f * (a3 + c5 - a5 - c3);
    const float dys = 0.25f * (e0 + e8 - e6 - e2);
    const float dxs = 0.25f * (a1 + c7 - a7 - c1);

    const float h00 = dxx, h01 = dxy, h02 = dxs;
    const float h10 = dxy, h11 = dyy, h12 = dys;
    const float h20 = dxs, h21 = dys, h22 = dss;
    const float b0 = gx, b1 = gy, b2 = gs;

    const float c00 = h11 * h22 - h12 * h21;
    const float c01 = h10 * h22 - h12 * h20;
    const float c02 = h10 * h21 - h11 * h20;
    const float det = h00 * c00 - h01 * c01 + h02 * c02;

    const float t1 = b1 * h22 - h12 * b2;
    const float t2 = b1 * h21 - h11 * b2;
    const float t3 = h10 * b2 - b1 * h20;

    const float inv = 1.0f / det;
    const float sx = (b0 * c00 - h01 * t1 + h02 * t2) * inv;
    const float sy = (h00 * t1 - b0 * c01 + h02 * t3) * inv;
    const float ss = (h00 * (h11 * b2 - h21 * b1) - h01 * t3 + b0 * c02) * inv;

    float d0 = -sx, d1 = -sy, d2 = -ss;
    const float far = fmaxf(fmaxf(fabsf(d0), fabsf(d1)), fabsf(d2));
    if (far > 0.7f) { d0 = 0.0f; d1 = 0.0f; d2 = 0.0f; }

    dx0 = d0; dx1 = d1; dx2 = d2;
    yv = cc + 0.5f * (gx * d0 + gy * d1 + gs * d2) + 10.0f;
}

__global__ __launch_bounds__(256, 3)   // keep 3 CTAs/SM (<=85 regs)
void quadinterp3d_kernel(const float* __restrict__ x, float* __restrict__ out) {
    // Block = 2 complete W-rows of 128 threads each; neighbors are adjacent tids.
    __shared__ float sCmX[256], sCmW[256], sV4X[256], sV4W[256];

    const int tid  = threadIdx.x;
    const int gid  = blockIdx.x * 256 + tid;
    const int w4 = gid & 127;            // 0..127, consecutive within a half-block row
    const int h  = (gid >> 7) & 511;
    const int t  = gid >> 16;            // 0..19 (B*D)
    const int d  = t % DD;
    const int b  = t / DD;
    const int w0 = w4 << 2;

    // Clamped stencil offsets via predicated deltas (replicate padding)
    const int off4 = (d * HH + h) * WW;
    const int dym = (h > 0)      ? WW : 0;
    const int dyp = (h < HH - 1) ? WW : 0;
    const int dzm = (d > 0)      ? HH * WW : 0;
    const int dzp = (d < DD - 1) ? HH * WW : 0;

    int off[9];
    off[0] = off4 - dzm - dym;  off[1] = off4 - dzm;  off[2] = off4 - dzm + dyp;
    off[3] = off4 - dym;        off[4] = off4;        off[5] = off4 + dyp;
    off[6] = off4 + dzp - dym;  off[7] = off4 + dzp;  off[8] = off4 + dzp + dyp;

    const float* __restrict__ base = x + (size_t)b * DD * HH * WW;

    // Batched independent loads: one aligned float4 per stencil row (MLP=9)
    float4 v[9];
    #pragma unroll
    for (int r = 0; r < 9; r++)
        v[r] = *reinterpret_cast<const float4*>(base + off[r] + w0);

    // Column max of the 8 non-center rows
    float4 cm = fmax4(fmax4(v[0], v[1]), fmax4(v[2], v[3]));
    cm = fmax4(cm, fmax4(fmax4(v[5], v[6]), fmax4(v[7], v[8])));

    // Block-level edge exchange (replaces shuffles + divergent lane fixups)
    sCmX[tid] = cm.x;  sCmW[tid] = cm.w;
    sV4X[tid] = v[4].x; sV4W[tid] = v[4].w;
    __syncthreads();

    const bool atL = (w4 == 0);
    const bool atR = (w4 == 127);
    const float cmL = atL ? cm.x   : sCmW[tid - 1];
    const float cmR = atR ? cm.w   : sCmX[tid + 1];
    const float r4l = atL ? v[4].x : sV4W[tid - 1];
    const float r4r = atR ? v[4].w : sV4X[tid + 1];

    // Windowed max over [cmL, cm.x, cm.y, cm.z, cm.w, cmR]
    const float p01 = fmaxf(cmL,  cm.x);
    const float p12 = fmaxf(cm.x, cm.y);
    const float p23 = fmaxf(cm.y, cm.z);
    const float p34 = fmaxf(cm.z, cm.w);
    const float win0 = fmaxf(p01, cm.y);
    const float win1 = fmaxf(p12, cm.z);
    const float win2 = fmaxf(p23, cm.w);
    const float win3 = fmaxf(p34, cmR);

    // Center-row contribution (excludes the center element itself)
    const float u0 = r4l, u1 = v[4].x, u2 = v[4].y, u3 = v[4].z, u4 = v[4].w, u5 = r4r;
    const float nm0 = fmaxf(fmaxf(win0, fmaxf(u0, u2)), 0.0f);
    const float nm1 = fmaxf(fmaxf(win1, fmaxf(u1, u3)), 0.0f);
    const float nm2 = fmaxf(fmaxf(win2, fmaxf(u2, u4)), 0.0f);
    const float nm3 = fmaxf(fmaxf(win3, fmaxf(u3, u5)), 0.0f);

    const bool m0 = u1 > nm0;
    const bool m1 = u2 > nm1;
    const bool m2 = u3 > nm2;
    const bool m3 = u4 > nm3;

    float A0 = 0.f, B0 = 0.f, C0 = 0.f, y0 = u1;
    float A1 = 0.f, B1 = 0.f, C1 = 0.f, y1 = u2;
    float A2 = 0.f, B2 = 0.f, C2 = 0.f, y2 = u3;
    float A3 = 0.f, B3 = 0.f, C3 = 0.f, y3 = u4;

    // Heavy path (~3.7% of voxels). Edge values for j=0/3 loaded lazily (L1 hits).
    if (m0) {
        const int wl = atL ? 0 : (w0 - 1);
        const float a1 = __ldg(base + off[1] + wl);
        const float a3 = __ldg(base + off[3] + wl);
        const float a5 = __ldg(base + off[5] + wl);
        const float a7 = __ldg(base + off[7] + wl);
        newton_step(u1, u0, v[4].y,
                    a3, v[3].x, v[3].y,
                    a5, v[5].x, v[5].y,
                    a1, v[1].x, v[1].y,
                    a7, v[7].x, v[7].y,
                    v[0].x, v[2].x, v[6].x, v[8].x,
                    A0, B0, C0, y0);
    }
    if (m1) {
        newton_step(u2, v[4].x, v[4].z,
                    v[3].x, v[3].y, v[3].z,
                    v[5].x, v[5].y, v[5].z,
                    v[1].x, v[1].y, v[1].z,
                    v[7].x, v[7].y, v[7].z,
                    v[0].y, v[2].y, v[6].y, v[8].y,
                    A1, B1, C1, y1);
    }
    if (m2) {
        newton_step(u3, v[4].y, v[4].w,
                    v[3].y, v[3].z, v[3].w,
                    v[5].y, v[5].z, v[5].w,
                    v[1].y, v[1].z, v[1].w,
                    v[7].y, v[7].z, v[7].w,
                    v[0].z, v[2].z, v[6].z, v[8].z,
                    A2, B2, C2, y2);
    }
    if (m3) {
        const int wr = atR ? (WW - 1) : (w0 + 4);
        const float c1 = __ldg(base + off[1] + wr);
        const float c3 = __ldg(base + off[3] + wr);
        const float c5 = __ldg(base + off[5] + wr);
        const float c7 = __ldg(base + off[7] + wr);
        newton_step(u4, v[4].z, u5,
                    v[3].z, v[3].w, c3,
                    v[5].z, v[5].w, c5,
                    v[1].z, v[1].w, c1,
                    v[7].z, v[7].w, c7,
                    v[0].w, v[2].w, v[6].w, v[8].w,
                    A3, B3, C3, y3);
    }

    // Coalesced float4 stores: coords (B,3,D,H,W) then y (B,D,H,W)
    const size_t plsz = (size_t)DD * HH * WW;
    const size_t inner = (size_t)off4 + w0;
    const float fd = (float)d, fh = (float)h, fw = (float)w0;
    *reinterpret_cast<float4*>(out + (size_t)(b * 3 + 0) * plsz + inner) =
        make_float4(fd + C0, fd + C1, fd + C2, fd + C3);
    *reinterpret_cast<float4*>(out + (size_t)(b * 3 + 1) * plsz + inner) =
        make_float4(fh + B0, fh + B1, fh + B2, fh + B3);
    *reinterpret_cast<float4*>(out + (size_t)(b * 3 + 2) * plsz + inner) =
        make_float4(fw + A0, fw + 1.0f + A1, fw + 2.0f + A2, fw + 3.0f + A3);
    *reinterpret_cast<float4*>(out + (size_t)BB * 3 * plsz + (size_t)b * plsz + inner) =
        make_float4(y0, y1, y2, y3);
}

extern "C" void kernel_launch(void* const* d_in, const int* in_sizes, int n_in,
                              void* d_out, int out_size) {
    const float* x = (const float*)d_in[0];
    float* out = (float*)d_out;
    const int total_threads = BB * DD * HH * (WW / 4);   // 1,310,720
    const int block = 256;
    const int grid = total_threads / block;              // 5,120
    quadinterp3d_kernel<<<grid, block>>>(x, out);
}

// round 6
// speedup vs baseline: 1.5468x; 1.0166x over previous
#include <cuda_runtime.h>
#include <cuda_bf16.h>

#define BB 2
#define DD 10
#define HH 512
#define WW 512

__device__ __forceinline__ float4 fmax4(float4 a, float4 b) {
    return make_float4(fmaxf(a.x, b.x), fmaxf(a.y, b.y), fmaxf(a.z, b.z), fmaxf(a.w, b.w));
}

// 3x3 Newton solve at a detected maximum. Same algebra as the verified kernels.
__device__ __forceinline__ void newton_step(
    float cc,
    float a4, float c4,                    // row4 (d,h)     at j, j+2
    float a3, float b3, float c3,          // row3 (d,h-1)   at j, j+1, j+2
    float a5, float b5, float c5,          // row5 (d,h+1)
    float a1, float b1v, float c1,         // row1 (d-1,h)
    float a7, float b7, float c7,          // row7 (d+1,h)
    float e0, float e2, float e6, float e8,// rows 0,2,6,8 at j+1
    float& dx0, float& dx1, float& dx2, float& yv)
{
    const float gx = 0.5f * (c4 - a4);
    const float gy = 0.5f * (b5 - b3);
    const float gs = 0.5f * (b7 - b1v);

    const float dxx = a4 + c4 - 2.0f * cc;
    const float dyy = b3 + b5 - 2.0f * cc;
    const float dss = b1v + b7 - 2.0f * cc;
    const float dxy = 0.25f * (a3 + c5 - a5 - c3);
    const float dys = 0.25f * (e0 + e8 - e6 - e2);
    const float dxs = 0.25f * (a1 + c7 - a7 - c1);

    const float h00 = dxx, h01 = dxy, h02 = dxs;
    const float h10 = dxy, h11 = dyy, h12 = dys;
    const float h20 = dxs, h21 = dys, h22 = dss;
    const float b0 = gx, b1 = gy, b2 = gs;

    const float c00 = h11 * h22 - h12 * h21;
    const float c01 = h10 * h22 - h12 * h20;
    const float c02 = h10 * h21 - h11 * h20;
    const float det = h00 * c00 - h01 * c01 + h02 * c02;

    const float t1 = b1 * h22 - h12 * b2;
    const float t2 = b1 * h21 - h11 * b2;
    const float t3 = h10 * b2 - b1 * h20;

    const float inv = 1.0f / det;
    const float sx = (b0 * c00 - h01 * t1 + h02 * t2) * inv;
    const float sy = (h00 * t1 - b0 * c01 + h02 * t3) * inv;
    const float ss = (h00 * (h11 * b2 - h21 * b1) - h01 * t3 + b0 * c02) * inv;

    float d0 = -sx, d1 = -sy, d2 = -ss;
    const float far = fmaxf(fmaxf(fabsf(d0), fabsf(d1)), fabsf(d2));
    if (far > 0.7f) { d0 = 0.0f; d1 = 0.0f; d2 = 0.0f; }

    dx0 = d0; dx1 = d1; dx2 = d2;
    yv = cc + 0.5f * (gx * d0 + gy * d1 + gs * d2) + 10.0f;
}

__global__ __launch_bounds__(256, 4)   // cap 64 regs: 4 CTAs/SM, 32 warps (latency hiding)
void quadinterp3d_kernel(const float* __restrict__ x, float* __restrict__ out) {
    // Block = 2 complete W-rows of 128 threads each; neighbors are adjacent tids.
    __shared__ float sCmX[256], sCmW[256], sV4X[256], sV4W[256];

    const int tid  = threadIdx.x;
    const int gid  = blockIdx.x * 256 + tid;
    const int w4 = gid & 127;            // 0..127, consecutive within a half-block row
    const int h  = (gid >> 7) & 511;
    const int t  = gid >> 16;            // 0..19 (B*D)
    const int d  = t % DD;
    const int b  = t / DD;
    const int w0 = w4 << 2;

    // Clamped stencil offsets via predicated deltas (replicate padding)
    const int off4 = (d * HH + h) * WW;
    const int dym = (h > 0)      ? WW : 0;
    const int dyp = (h < HH - 1) ? WW : 0;
    const int dzm = (d > 0)      ? HH * WW : 0;
    const int dzp = (d < DD - 1) ? HH * WW : 0;

    int off[9];
    off[0] = off4 - dzm - dym;  off[1] = off4 - dzm;  off[2] = off4 - dzm + dyp;
    off[3] = off4 - dym;        off[4] = off4;        off[5] = off4 + dyp;
    off[6] = off4 + dzp - dym;  off[7] = off4 + dzp;  off[8] = off4 + dzp + dyp;

    const float* __restrict__ base = x + (size_t)b * DD * HH * WW;

    // Batched independent loads: one aligned float4 per stencil row (MLP=9)
    float4 v[9];
    #pragma unroll
    for (int r = 0; r < 9; r++)
        v[r] = *reinterpret_cast<const float4*>(base + off[r] + w0);

    // Column max of the 8 non-center rows
    float4 cm = fmax4(fmax4(v[0], v[1]), fmax4(v[2], v[3]));
    cm = fmax4(cm, fmax4(fmax4(v[5], v[6]), fmax4(v[7], v[8])));

    // Block-level edge exchange (replaces shuffles + divergent lane fixups)
    sCmX[tid] = cm.x;  sCmW[tid] = cm.w;
    sV4X[tid] = v[4].x; sV4W[tid] = v[4].w;
    __syncthreads();

    const bool atL = (w4 == 0);
    const bool atR = (w4 == 127);
    const float cmL = atL ? cm.x   : sCmW[tid - 1];
    const float cmR = atR ? cm.w   : sCmX[tid + 1];
    const float r4l = atL ? v[4].x : sV4W[tid - 1];
    const float r4r = atR ? v[4].w : sV4X[tid + 1];

    // Windowed max over [cmL, cm.x, cm.y, cm.z, cm.w, cmR]
    const float p01 = fmaxf(cmL,  cm.x);
    const float p12 = fmaxf(cm.x, cm.y);
    const float p23 = fmaxf(cm.y, cm.z);
    const float p34 = fmaxf(cm.z, cm.w);
    const float win0 = fmaxf(p01, cm.y);
    const float win1 = fmaxf(p12, cm.z);
    const float win2 = fmaxf(p23, cm.w);
    const float win3 = fmaxf(p34, cmR);

    // Center-row contribution (excludes the center element itself)
    const float u0 = r4l, u1 = v[4].x, u2 = v[4].y, u3 = v[4].z, u4 = v[4].w, u5 = r4r;
    const float nm0 = fmaxf(fmaxf(win0, fmaxf(u0, u2)), 0.0f);
    const float nm1 = fmaxf(fmaxf(win1, fmaxf(u1, u3)), 0.0f);
    const float nm2 = fmaxf(fmaxf(win2, fmaxf(u2, u4)), 0.0f);
    const float nm3 = fmaxf(fmaxf(win3, fmaxf(u3, u5)), 0.0f);

    const bool m0 = u1 > nm0;
    const bool m1 = u2 > nm1;
    const bool m2 = u3 > nm2;
    const bool m3 = u4 > nm3;

    float A0 = 0.f, B0 = 0.f, C0 = 0.f, y0 = u1;
    float A1 = 0.f, B1 = 0.f, C1 = 0.f, y1 = u2;
    float A2 = 0.f, B2 = 0.f, C2 = 0.f, y2 = u3;
    float A3 = 0.f, B3 = 0.f, C3 = 0.f, y3 = u4;

    // Heavy path (~3.7% of voxels). Edge values for j=0/3 loaded lazily (L1 hits).
    if (m0) {
        const int wl = atL ? 0 : (w0 - 1);
        const float a1 = __ldg(base + off[1] + wl);
        const float a3 = __ldg(base + off[3] + wl);
        const float a5 = __ldg(base + off[5] + wl);
        const float a7 = __ldg(base + off[7] + wl);
        newton_step(u1, u0, v[4].y,
                    a3, v[3].x, v[3].y,
                    a5, v[5].x, v[5].y,
                    a1, v[1].x, v[1].y,
                    a7, v[7].x, v[7].y,
                    v[0].x, v[2].x, v[6].x, v[8].x,
                    A0, B0, C0, y0);
    }
    if (m1) {
        newton_step(u2, v[4].x, v[4].z,
                    v[3].x, v[3].y, v[3].z,
                    v[5].x, v[5].y, v[5].z,
                    v[1].x, v[1].y, v[1].z,
                    v[7].x, v[7].y, v[7].z,
                    v[0].y, v[2].y, v[6].y, v[8].y,
                    A1, B1, C1, y1);
    }
    if (m2) {
        newton_step(u3, v[4].y, v[4].w,
                    v[3].y, v[3].z, v[3].w,
                    v[5].y, v[5].z, v[5].w,
                    v[1].y, v[1].z, v[1].w,
                    v[7].y, v[7].z, v[7].w,
                    v[0].z, v[2].z, v[6].z, v[8].z,
                    A2, B2, C2, y2);
    }
    if (m3) {
        const int wr = atR ? (WW - 1) : (w0 + 4);
        const float c1 = __ldg(base + off[1] + wr);
        const float c3 = __ldg(base + off[3] + wr);
        const float c5 = __ldg(base + off[5] + wr);
        const float c7 = __ldg(base + off[7] + wr);
        newton_step(u4, v[4].z, u5,
                    v[3].z, v[3].w, c3,
                    v[5].z, v[5].w, c5,
                    v[1].z, v[1].w, c1,
                    v[7].z, v[7].w, c7,
                    v[0].w, v[2].w, v[6].w, v[8].w,
                    A3, B3, C3, y3);
    }

    // Coalesced float4 stores: coords (B,3,D,H,W) then y (B,D,H,W)
    const size_t plsz = (size_t)DD * HH * WW;
    const size_t inner = (size_t)off4 + w0;
    const float fd = (float)d, fh = (float)h, fw = (float)w0;
    *reinterpret_cast<float4*>(out + (size_t)(b * 3 + 0) * plsz + inner) =
        make_float4(fd + C0, fd + C1, fd + C2, fd + C3);
    *reinterpret_cast<float4*>(out + (size_t)(b * 3 + 1) * plsz + inner) =
        make_float4(fh + B0, fh + B1, fh + B2, fh + B3);
    *reinterpret_cast<float4*>(out + (size_t)(b * 3 + 2) * plsz + inner) =
        make_float4(fw + A0, fw + 1.0f + A1, fw + 2.0f + A2, fw + 3.0f + A3);
    *reinterpret_cast<float4*>(out + (size_t)BB * 3 * plsz + (size_t)b * plsz + inner) =
        make_float4(y0, y1, y2, y3);
}

extern "C" void kernel_launch(void* const* d_in, const int* in_sizes, int n_in,
                              void* d_out, int out_size) {
    const float* x = (const float*)d_in[0];
    float* out = (float*)d_out;
    const int total_threads = BB * DD * HH * (WW / 4);   // 1,310,720
    const int block = 256;
    const int grid = total_threads / block;              // 5,120
    quadinterp3d_kernel<<<grid, block>>>(x, out);
}